// round 6
// baseline (speedup 1.0000x reference)
#include <cuda_runtime.h>
#include <cuda_bf16.h>
#include <cstdint>
#include <cstddef>

#define NSTEP 32768
#define HH 128
#define G3 384
#define KDIM 530
#define EDIM 512
#define ADIM 18
#define FCDIM 256

__device__ float g_gi_pred[(size_t)NSTEP * G3];
__device__ float g_gi_true[(size_t)NSTEP * G3];
__device__ float g_hpred[(size_t)NSTEP * HH];

__device__ __forceinline__ float sigf(float x) {
    return __fdividef(1.f, 1.f + __expf(-x));
}
__device__ __forceinline__ float tanhf_fast(float x) {
    return __fdividef(2.f, 1.f + __expf(-2.f * x)) - 1.f;
}
__device__ __forceinline__ void cpa16(unsigned dst, const void* src) {
    asm volatile("cp.async.cg.shared.global [%0], [%1], 16;" :: "r"(dst), "l"(src));
}
__device__ __forceinline__ uint32_t pkbf(float x, float y) {
    __nv_bfloat162 v;
    v.x = __float2bfloat16(x);
    v.y = __float2bfloat16(y);
    return *reinterpret_cast<uint32_t*>(&v);
}

#define MMA16816(c, a, b0v, b1v) \
    asm volatile("mma.sync.aligned.m16n8k16.row.col.f32.bf16.bf16.f32 " \
        "{%0,%1,%2,%3}, {%4,%5,%6,%7}, {%8,%9}, {%0,%1,%2,%3};" \
        : "+f"((c)[0]), "+f"((c)[1]), "+f"((c)[2]), "+f"((c)[3]) \
        : "r"((a)[0]), "r"((a)[1]), "r"((a)[2]), "r"((a)[3]), "r"(b0v), "r"(b1v))

// ============================================================================
// Kernel 1: gi = concat(enc, act) @ Wih.T + bih  (unchanged)
// ============================================================================
__global__ void __launch_bounds__(256) gi_gemm(
    const float* __restrict__ encp, const float* __restrict__ enct,
    const float* __restrict__ act,  const float* __restrict__ Wih,
    const float* __restrict__ bih)
{
    const float* A = blockIdx.z ? enct : encp;
    float* C = blockIdx.z ? g_gi_true : g_gi_pred;

    __shared__ __align__(16) float As[16][68];
    __shared__ __align__(16) float Bs[16][68];

    int t = threadIdx.x;
    int m0 = blockIdx.x * 64, n0 = blockIdx.y * 64;
    int tx = t & 15, ty = t >> 4;
    int arow = t >> 2, ac4 = (t & 3) * 4;

    float acc[4][4];
#pragma unroll
    for (int a = 0; a < 4; a++)
#pragma unroll
        for (int b = 0; b < 4; b++) acc[a][b] = 0.f;

    for (int kt = 0; kt < 34; kt++) {
        int k0 = kt * 16;
        float av[4], bv[4];
        if (k0 < EDIM) {
            float4 v = *(const float4*)(A + (size_t)(m0 + arow) * EDIM + k0 + ac4);
            av[0] = v.x; av[1] = v.y; av[2] = v.z; av[3] = v.w;
            const float* bp = Wih + (size_t)(n0 + arow) * KDIM + k0 + ac4;
            float2 u0 = *(const float2*)(bp);
            float2 u1 = *(const float2*)(bp + 2);
            bv[0] = u0.x; bv[1] = u0.y; bv[2] = u1.x; bv[3] = u1.y;
        } else {
#pragma unroll
            for (int j = 0; j < 4; j++) {
                int kg = k0 + ac4 + j;
                av[j] = (kg < KDIM) ? act[(size_t)(m0 + arow) * ADIM + (kg - EDIM)] : 0.f;
                bv[j] = (kg < KDIM) ? Wih[(size_t)(n0 + arow) * KDIM + kg] : 0.f;
            }
        }
        __syncthreads();
#pragma unroll
        for (int j = 0; j < 4; j++) { As[ac4 + j][arow] = av[j]; Bs[ac4 + j][arow] = bv[j]; }
        __syncthreads();
#pragma unroll
        for (int kk = 0; kk < 16; kk++) {
            float4 a4 = *(const float4*)&As[kk][ty * 4];
            float4 b4 = *(const float4*)&Bs[kk][tx * 4];
            float ar[4] = {a4.x, a4.y, a4.z, a4.w};
            float br[4] = {b4.x, b4.y, b4.z, b4.w};
#pragma unroll
            for (int r = 0; r < 4; r++)
#pragma unroll
                for (int cc = 0; cc < 4; cc++) acc[r][cc] += ar[r] * br[cc];
        }
    }
#pragma unroll
    for (int r = 0; r < 4; r++) {
        int m = m0 + ty * 4 + r;
#pragma unroll
        for (int cc = 0; cc < 4; cc++) {
            int n = n0 + tx * 4 + cc;
            C[(size_t)m * G3 + n] = acc[r][cc] + bih[n];
        }
    }
}

// ============================================================================
// Kernel 2: GRU scan via mma.sync bf16 hi/lo split. 1 CTA, 384 threads.
// R6 change: per tile, accumulate ks 0-7 and ks 8-15 into INDEPENDENT
// fragment chains (4 chains/warp total), summed at the end -> breaks the
// 16..32-deep HMMA dependency chain that latency-bound R5.
// ============================================================================
__global__ void __launch_bounds__(384, 1) gru_scan_mma(
    const float* __restrict__ Whh, const float* __restrict__ bhh,
    const float* __restrict__ h0)
{
    __shared__ __align__(16) float ring[4][768];   // [pred 384 | true 384] per slot
    __shared__ float gh_sm[384];
    __shared__ float h_sm[2][HH];
    __shared__ uint32_t hi_pack[2][64];
    __shared__ uint32_t lo_pack[2][64];

    int t = threadIdx.x;
    int lane = t & 31;
    int w = t >> 5;

    // ---- Load A fragments (one-time): 2 tiles x 16 ksteps x 4 regs ----
    uint32_t afr[2][16][4];
#pragma unroll
    for (int tile = 0; tile < 2; tile++) {
        int ft = 2 * w + tile;
        int g = ft >> 3, m = ft & 7;
        int r0 = 16 * m + (lane >> 2);
        const float* Wg = Whh + (size_t)g * HH * HH;
#pragma unroll
        for (int ks = 0; ks < 8; ks++) {
            int kc = 16 * ks + 2 * (lane & 3);
            float v[8];
            v[0] = Wg[(size_t)r0 * HH + kc];
            v[1] = Wg[(size_t)r0 * HH + kc + 1];
            v[2] = Wg[(size_t)(r0 + 8) * HH + kc];
            v[3] = Wg[(size_t)(r0 + 8) * HH + kc + 1];
            v[4] = Wg[(size_t)r0 * HH + kc + 8];
            v[5] = Wg[(size_t)r0 * HH + kc + 9];
            v[6] = Wg[(size_t)(r0 + 8) * HH + kc + 8];
            v[7] = Wg[(size_t)(r0 + 8) * HH + kc + 9];
            float hi[8], lo[8];
#pragma unroll
            for (int j = 0; j < 8; j++) {
                hi[j] = __bfloat162float(__float2bfloat16(v[j]));
                lo[j] = v[j] - hi[j];
            }
            afr[tile][ks][0] = pkbf(hi[0], hi[1]);
            afr[tile][ks][1] = pkbf(hi[2], hi[3]);
            afr[tile][ks][2] = pkbf(hi[4], hi[5]);
            afr[tile][ks][3] = pkbf(hi[6], hi[7]);
            afr[tile][ks + 8][0] = pkbf(lo[0], lo[1]);
            afr[tile][ks + 8][1] = pkbf(lo[2], lo[3]);
            afr[tile][ks + 8][2] = pkbf(lo[4], lo[5]);
            afr[tile][ks + 8][3] = pkbf(lo[6], lo[7]);
        }
    }

    int hb = t & 127;
    float br = bhh[hb], bz = bhh[HH + hb], bn = bhh[2 * HH + hb];

    if (t < HH) {
        float h = h0[t];
        h_sm[0][t] = h;
        __nv_bfloat16 bhi = __float2bfloat16(h);
        __nv_bfloat16 blo = __float2bfloat16(h - __bfloat162float(bhi));
        ((__nv_bfloat16*)hi_pack[0])[t] = bhi;
        ((__nv_bfloat16*)lo_pack[0])[t] = blo;
    }

    // ---- Ring prefill: slots 0,1,2 ----
#pragma unroll
    for (int k = 0; k < 3; k++) {
        unsigned dst = (unsigned)__cvta_generic_to_shared(&ring[k][0]);
        if (t < 96) cpa16(dst + t * 16, (const char*)(g_gi_pred + (size_t)k * G3) + t * 16);
        else if (t < 192) cpa16(dst + 1536 + (t - 96) * 16,
                                (const char*)(g_gi_true + (size_t)k * G3) + (t - 96) * 16);
        asm volatile("cp.async.commit_group;");
    }
    asm volatile("cp.async.wait_group 2;" ::: "memory");
    __syncthreads();

    for (int s = 0; s < NSTEP; s++) {
        // ---- HMMA matvec phase: 4 independent chains of 8 MMAs ----
        float c0a[4] = {0.f, 0.f, 0.f, 0.f};
        float c0b[4] = {0.f, 0.f, 0.f, 0.f};
        float c1a[4] = {0.f, 0.f, 0.f, 0.f};
        float c1b[4] = {0.f, 0.f, 0.f, 0.f};
        const uint32_t* hp = hi_pack[s & 1];
        const uint32_t* lp = lo_pack[s & 1];
#pragma unroll
        for (int ks = 0; ks < 8; ks++) {
            uint32_t b0 = 0, b1 = 0;
            if (lane < 8) {
                const uint32_t* pa = (lane >= 4) ? lp : hp;
                int bi = (ks << 3) + (lane & 3);
                b0 = pa[bi];
                b1 = pa[bi + 4];
            }
            MMA16816(c0a, afr[0][ks], b0, b1);      // tile0, hi rows
            MMA16816(c1a, afr[1][ks], b0, b1);      // tile1, hi rows
            MMA16816(c0b, afr[0][ks + 8], b0, b1);  // tile0, lo rows
            MMA16816(c1b, afr[1][ks + 8], b0, b1);  // tile1, lo rows
        }
        if ((lane & 3) == 0) {
            int r = lane >> 2;
            int ft0 = 2 * w, ft1 = 2 * w + 1;
            int base0 = (ft0 >> 3) * 128 + (ft0 & 7) * 16 + r;
            int base1 = (ft1 >> 3) * 128 + (ft1 & 7) * 16 + r;
            gh_sm[base0]     = (c0a[0] + c0b[0]) + (c0a[1] + c0b[1]);
            gh_sm[base0 + 8] = (c0a[2] + c0b[2]) + (c0a[3] + c0b[3]);
            gh_sm[base1]     = (c1a[0] + c1b[0]) + (c1a[1] + c1b[1]);
            gh_sm[base1 + 8] = (c1a[2] + c1b[2]) + (c1a[3] + c1b[3]);
        }
        __syncthreads();

        // ---- prefetch slot s+3 ----
        if (s + 3 < NSTEP) {
            unsigned dst = (unsigned)__cvta_generic_to_shared(&ring[(s + 3) & 3][0]);
            if (t < 96) cpa16(dst + t * 16, (const char*)(g_gi_pred + (size_t)(s + 3) * G3) + t * 16);
            else if (t < 192) cpa16(dst + 1536 + (t - 96) * 16,
                                    (const char*)(g_gi_true + (size_t)(s + 3) * G3) + (t - 96) * 16);
        }
        asm volatile("cp.async.commit_group;");
        asm volatile("cp.async.wait_group 2;" ::: "memory");

        // ---- activation phase ----
        int nb = (s + 1) & 1;
        if (t < HH) {
            // true path -> next state
            float ghr = gh_sm[t] + br, ghz = gh_sm[HH + t] + bz, ghn = gh_sm[2 * HH + t] + bn;
            const float* rg = ring[s & 3];
            float hprev = h_sm[s & 1][t];
            float r2 = sigf(rg[384 + t] + ghr);
            float z2 = sigf(rg[512 + t] + ghz);
            float n2 = tanhf_fast(rg[640 + t] + r2 * ghn);
            float hnew = (1.f - z2) * n2 + z2 * hprev;
            h_sm[nb][t] = hnew;
            __nv_bfloat16 bhi = __float2bfloat16(hnew);
            __nv_bfloat16 blo = __float2bfloat16(hnew - __bfloat162float(bhi));
            ((__nv_bfloat16*)hi_pack[nb])[t] = bhi;
            ((__nv_bfloat16*)lo_pack[nb])[t] = blo;
        } else if (t < 256) {
            // pred path -> output
            int j = t - HH;
            float ghr = gh_sm[j] + br, ghz = gh_sm[HH + j] + bz, ghn = gh_sm[2 * HH + j] + bn;
            const float* rg = ring[s & 3];
            float hprev = h_sm[s & 1][j];
            float r1 = sigf(rg[j] + ghr);
            float z1 = sigf(rg[HH + j] + ghz);
            float n1 = tanhf_fast(rg[2 * HH + j] + r1 * ghn);
            g_hpred[(size_t)s * HH + j] = (1.f - z1) * n1 + z1 * hprev;
        }
        __syncthreads();
    }
}

// ============================================================================
// Kernel 3: MLP head (unchanged)
// ============================================================================
__global__ void __launch_bounds__(256) mlp_head(
    const float* __restrict__ fc1w, const float* __restrict__ fc1b,
    const float* __restrict__ fc2w, const float* __restrict__ fc2b,
    float* __restrict__ out)
{
    extern __shared__ float sm[];
    float* w1  = sm;
    float* b1  = sm + FCDIM * HH;
    float* w2  = b1 + FCDIM;
    float* hs  = w2 + FCDIM;
    float* red = hs + HH;

    int t = threadIdx.x;
    for (int idx = t; idx < FCDIM * HH; idx += 256) w1[idx] = fc1w[idx];
    b1[t] = fc1b[t];
    w2[t] = fc2w[t];
    __syncthreads();

    float myb = b1[t], myw2 = w2[t];
    const float4* wj = (const float4*)(w1 + t * HH);

    for (int r = 0; r < 64; r++) {
        size_t row = (size_t)blockIdx.x * 64 + r;
        if (t < HH) hs[t] = g_hpred[row * HH + t];
        __syncthreads();
        float acc = 0.f;
        const float4* hv = (const float4*)hs;
#pragma unroll
        for (int q = 0; q < 32; q++) {
            float4 a = wj[q], b = hv[q];
            acc += a.x * b.x; acc += a.y * b.y; acc += a.z * b.z; acc += a.w * b.w;
        }
        float v = acc + myb;
        v = v > 0.f ? v : 0.f;
        v *= myw2;
#pragma unroll
        for (int m = 16; m; m >>= 1) v += __shfl_xor_sync(0xffffffffu, v, m);
        if ((t & 31) == 0) red[t >> 5] = v;
        __syncthreads();
        if (t == 0) {
            float sv = red[0] + red[1] + red[2] + red[3] +
                       red[4] + red[5] + red[6] + red[7] + fc2b[0];
            out[row] = 1.f / (1.f + __expf(-sv));
        }
        __syncthreads();
    }
}

extern "C" void kernel_launch(void* const* d_in, const int* in_sizes, int n_in,
                              void* d_out, int out_size) {
    const float* enc  = (const float*)d_in[0];
    const float* act  = (const float*)d_in[1];
    const float* tru  = (const float*)d_in[2];
    const float* Wih  = (const float*)d_in[3];
    const float* Whh  = (const float*)d_in[4];
    const float* bih  = (const float*)d_in[5];
    const float* bhh  = (const float*)d_in[6];
    const float* h0   = (const float*)d_in[7];
    const float* fc1w = (const float*)d_in[8];
    const float* fc1b = (const float*)d_in[9];
    const float* fc2w = (const float*)d_in[10];
    const float* fc2b = (const float*)d_in[11];
    float* out = (float*)d_out;

    int mlp_smem = (FCDIM * HH + FCDIM + FCDIM + HH + 8) * 4;
    cudaFuncSetAttribute(mlp_head, cudaFuncAttributeMaxDynamicSharedMemorySize, mlp_smem);

    dim3 g(512, 6, 2);
    gi_gemm<<<g, 256>>>(enc, tru, act, Wih, bih);
    gru_scan_mma<<<1, 384>>>(Whh, bhh, h0);
    mlp_head<<<512, 256, mlp_smem>>>(fc1w, fc1b, fc2w, fc2b, out);
}

// round 7
// speedup vs baseline: 1.4526x; 1.4526x over previous
#include <cuda_runtime.h>
#include <cuda_bf16.h>
#include <cstdint>
#include <cstddef>

#define NSTEP 32768
#define HH 128
#define G3 384
#define KDIM 530
#define EDIM 512
#define ADIM 18
#define FCDIM 256

__device__ float g_gi_pred[(size_t)NSTEP * G3];
__device__ float g_gi_true[(size_t)NSTEP * G3];
__device__ float g_hpred[(size_t)NSTEP * HH];

typedef unsigned long long ull;

__device__ __forceinline__ ull ffma2(ull a, ull b, ull c) {
    ull d;
    asm("fma.rn.f32x2 %0, %1, %2, %3;" : "=l"(d) : "l"(a), "l"(b), "l"(c));
    return d;
}
__device__ __forceinline__ float plo(ull a) { return __uint_as_float((unsigned)a); }
__device__ __forceinline__ float phi(ull a) { return __uint_as_float((unsigned)(a >> 32)); }
__device__ __forceinline__ float sigf(float x) {
    return __fdividef(1.f, 1.f + __expf(-x));
}
__device__ __forceinline__ float tanhf_fast(float x) {
    return __fdividef(2.f, 1.f + __expf(-2.f * x)) - 1.f;
}

// ============================================================================
// Kernel 1: gi = concat(enc, act) @ Wih.T + bih  (unchanged, proven)
// ============================================================================
__global__ void __launch_bounds__(256) gi_gemm(
    const float* __restrict__ encp, const float* __restrict__ enct,
    const float* __restrict__ act,  const float* __restrict__ Wih,
    const float* __restrict__ bih)
{
    const float* A = blockIdx.z ? enct : encp;
    float* C = blockIdx.z ? g_gi_true : g_gi_pred;

    __shared__ __align__(16) float As[16][68];
    __shared__ __align__(16) float Bs[16][68];

    int t = threadIdx.x;
    int m0 = blockIdx.x * 64, n0 = blockIdx.y * 64;
    int tx = t & 15, ty = t >> 4;
    int arow = t >> 2, ac4 = (t & 3) * 4;

    float acc[4][4];
#pragma unroll
    for (int a = 0; a < 4; a++)
#pragma unroll
        for (int b = 0; b < 4; b++) acc[a][b] = 0.f;

    for (int kt = 0; kt < 34; kt++) {
        int k0 = kt * 16;
        float av[4], bv[4];
        if (k0 < EDIM) {
            float4 v = *(const float4*)(A + (size_t)(m0 + arow) * EDIM + k0 + ac4);
            av[0] = v.x; av[1] = v.y; av[2] = v.z; av[3] = v.w;
            const float* bp = Wih + (size_t)(n0 + arow) * KDIM + k0 + ac4;
            float2 u0 = *(const float2*)(bp);
            float2 u1 = *(const float2*)(bp + 2);
            bv[0] = u0.x; bv[1] = u0.y; bv[2] = u1.x; bv[3] = u1.y;
        } else {
#pragma unroll
            for (int j = 0; j < 4; j++) {
                int kg = k0 + ac4 + j;
                av[j] = (kg < KDIM) ? act[(size_t)(m0 + arow) * ADIM + (kg - EDIM)] : 0.f;
                bv[j] = (kg < KDIM) ? Wih[(size_t)(n0 + arow) * KDIM + kg] : 0.f;
            }
        }
        __syncthreads();
#pragma unroll
        for (int j = 0; j < 4; j++) { As[ac4 + j][arow] = av[j]; Bs[ac4 + j][arow] = bv[j]; }
        __syncthreads();
#pragma unroll
        for (int kk = 0; kk < 16; kk++) {
            float4 a4 = *(const float4*)&As[kk][ty * 4];
            float4 b4 = *(const float4*)&Bs[kk][tx * 4];
            float ar[4] = {a4.x, a4.y, a4.z, a4.w};
            float br[4] = {b4.x, b4.y, b4.z, b4.w};
#pragma unroll
            for (int r = 0; r < 4; r++)
#pragma unroll
                for (int cc = 0; cc < 4; cc++) acc[r][cc] += ar[r] * br[cc];
        }
    }
#pragma unroll
    for (int r = 0; r < 4; r++) {
        int m = m0 + ty * 4 + r;
#pragma unroll
        for (int cc = 0; cc < 4; cc++) {
            int n = n0 + tx * 4 + cc;
            C[(size_t)m * G3 + n] = acc[r][cc] + bih[n];
        }
    }
}

// ============================================================================
// Kernel 2: sequential GRU scan (R3 architecture, ring removed).
// 256 threads: thread (i=t>>1, c=t&1) owns Whh rows {i,128+i,256+i},
// cols [c*64, c*64+64) in 192 weight regs; packed FFMA2; 1 shfl reduce;
// c==0 -> pred output, c==1 -> state update.
// gi prefetched 4 steps ahead via plain LDG into register buffers (x4 unroll).
// ============================================================================
__global__ void __launch_bounds__(256, 1) gru_scan(
    const float* __restrict__ Whh, const float* __restrict__ bhh,
    const float* __restrict__ h0)
{
    __shared__ __align__(16) float hbuf[2][HH];

    int t = threadIdx.x;
    int i = t >> 1;
    int c = t & 1;

    // Register-resident weights: 3 gates x 64 contiguous columns = 96 ull
    ull wr[32], wz[32], wn[32];
    {
        const ull* pr = (const ull*)(Whh + (size_t)i * HH + c * 64);
        const ull* pz = (const ull*)(Whh + (size_t)(HH + i) * HH + c * 64);
        const ull* pn = (const ull*)(Whh + (size_t)(2 * HH + i) * HH + c * 64);
#pragma unroll
        for (int q = 0; q < 32; q++) { wr[q] = pr[q]; wz[q] = pz[q]; wn[q] = pn[q]; }
    }
    float br = bhh[i], bz = bhh[HH + i], bn = bhh[2 * HH + i];
    if (t < HH) hbuf[0][t] = h0[t];

    // gi register prefetch: c==0 -> pred triple, c==1 -> true triple
    const float* gsrc = c ? (g_gi_true + i) : (g_gi_pred + i);
    float gA[3], gB[3], gC[3], gD[3];
#pragma unroll
    for (int j = 0; j < 3; j++) {
        gA[j] = __ldg(gsrc + 0 * G3 + j * HH);
        gB[j] = __ldg(gsrc + 1 * G3 + j * HH);
        gC[j] = __ldg(gsrc + 2 * G3 + j * HH);
        gD[j] = __ldg(gsrc + 3 * G3 + j * HH);
    }
    __syncthreads();

#define GRU_BODY(STEP, GBUF, PIN, POUT)                                          \
    {                                                                            \
        const ulonglong2* hp2 = (const ulonglong2*)(hbuf[PIN] + c * 64);         \
        ull ar = 0, az = 0, an = 0;                                              \
        _Pragma("unroll")                                                        \
        for (int q = 0; q < 16; q++) {                                           \
            ulonglong2 hq = hp2[q];                                              \
            ar = ffma2(wr[2 * q],     hq.x, ar);                                 \
            az = ffma2(wz[2 * q],     hq.x, az);                                 \
            an = ffma2(wn[2 * q],     hq.x, an);                                 \
            ar = ffma2(wr[2 * q + 1], hq.y, ar);                                 \
            az = ffma2(wz[2 * q + 1], hq.y, az);                                 \
            an = ffma2(wn[2 * q + 1], hq.y, an);                                 \
        }                                                                        \
        float sr = plo(ar) + phi(ar);                                            \
        float sz = plo(az) + phi(az);                                            \
        float sn = plo(an) + phi(an);                                            \
        sr += __shfl_xor_sync(0xffffffffu, sr, 1);                               \
        sz += __shfl_xor_sync(0xffffffffu, sz, 1);                               \
        sn += __shfl_xor_sync(0xffffffffu, sn, 1);                               \
        float ghr = sr + br, ghz = sz + bz, ghn = sn + bn;                       \
        float hprev = hbuf[PIN][i];                                              \
        float r = sigf(GBUF[0] + ghr);                                           \
        float z = sigf(GBUF[1] + ghz);                                           \
        float n = tanhf_fast(GBUF[2] + r * ghn);                                 \
        float hnew = (1.f - z) * n + z * hprev;                                  \
        if (c) hbuf[POUT][i] = hnew;                                             \
        else   g_hpred[(size_t)(STEP) * HH + i] = hnew;                          \
        if ((STEP) + 4 < NSTEP) {                                                \
            const float* srcn = gsrc + (size_t)((STEP) + 4) * G3;                \
            GBUF[0] = __ldg(srcn);                                               \
            GBUF[1] = __ldg(srcn + HH);                                          \
            GBUF[2] = __ldg(srcn + 2 * HH);                                      \
        }                                                                        \
        __syncthreads();                                                         \
    }

    for (int s = 0; s < NSTEP; s += 4) {
        GRU_BODY(s + 0, gA, 0, 1)
        GRU_BODY(s + 1, gB, 1, 0)
        GRU_BODY(s + 2, gC, 0, 1)
        GRU_BODY(s + 3, gD, 1, 0)
    }
#undef GRU_BODY
}

// ============================================================================
// Kernel 3: MLP head (unchanged, proven)
// ============================================================================
__global__ void __launch_bounds__(256) mlp_head(
    const float* __restrict__ fc1w, const float* __restrict__ fc1b,
    const float* __restrict__ fc2w, const float* __restrict__ fc2b,
    float* __restrict__ out)
{
    extern __shared__ float sm[];
    float* w1  = sm;
    float* b1  = sm + FCDIM * HH;
    float* w2  = b1 + FCDIM;
    float* hs  = w2 + FCDIM;
    float* red = hs + HH;

    int t = threadIdx.x;
    for (int idx = t; idx < FCDIM * HH; idx += 256) w1[idx] = fc1w[idx];
    b1[t] = fc1b[t];
    w2[t] = fc2w[t];
    __syncthreads();

    float myb = b1[t], myw2 = w2[t];
    const float4* wj = (const float4*)(w1 + t * HH);

    for (int r = 0; r < 64; r++) {
        size_t row = (size_t)blockIdx.x * 64 + r;
        if (t < HH) hs[t] = g_hpred[row * HH + t];
        __syncthreads();
        float acc = 0.f;
        const float4* hv = (const float4*)hs;
#pragma unroll
        for (int q = 0; q < 32; q++) {
            float4 a = wj[q], b = hv[q];
            acc += a.x * b.x; acc += a.y * b.y; acc += a.z * b.z; acc += a.w * b.w;
        }
        float v = acc + myb;
        v = v > 0.f ? v : 0.f;
        v *= myw2;
#pragma unroll
        for (int m = 16; m; m >>= 1) v += __shfl_xor_sync(0xffffffffu, v, m);
        if ((t & 31) == 0) red[t >> 5] = v;
        __syncthreads();
        if (t == 0) {
            float sv = red[0] + red[1] + red[2] + red[3] +
                       red[4] + red[5] + red[6] + red[7] + fc2b[0];
            out[row] = 1.f / (1.f + __expf(-sv));
        }
        __syncthreads();
    }
}

extern "C" void kernel_launch(void* const* d_in, const int* in_sizes, int n_in,
                              void* d_out, int out_size) {
    const float* enc  = (const float*)d_in[0];
    const float* act  = (const float*)d_in[1];
    const float* tru  = (const float*)d_in[2];
    const float* Wih  = (const float*)d_in[3];
    const float* Whh  = (const float*)d_in[4];
    const float* bih  = (const float*)d_in[5];
    const float* bhh  = (const float*)d_in[6];
    const float* h0   = (const float*)d_in[7];
    const float* fc1w = (const float*)d_in[8];
    const float* fc1b = (const float*)d_in[9];
    const float* fc2w = (const float*)d_in[10];
    const float* fc2b = (const float*)d_in[11];
    float* out = (float*)d_out;

    int mlp_smem = (FCDIM * HH + FCDIM + FCDIM + HH + 8) * 4;
    cudaFuncSetAttribute(mlp_head, cudaFuncAttributeMaxDynamicSharedMemorySize, mlp_smem);

    dim3 g(512, 6, 2);
    gi_gemm<<<g, 256>>>(enc, tru, act, Wih, bih);
    gru_scan<<<1, 256>>>(Whh, bhh, h0);
    mlp_head<<<512, 256, mlp_smem>>>(fc1w, fc1b, fc2w, fc2b, out);
}